// round 12
// baseline (speedup 1.0000x reference)
#include <cuda_runtime.h>
#include <math.h>

#define PI_F     3.14159265358979f
#define INVPI_F  0.3183098861837907f
#define EPS_F    1e-12f
#define NPTS     1000
#define KTAIL    64                 // last KTAIL disconnected-grid terms: exact per element
#define KSPLIT   (NPTS - KTAIL)     // 936
#define TABN     1024
#define MINV     2048               // inverse-index table size
#define ZLO      1e-4f
#define ZHI      0.9995f
#define DZ       ((ZHI - ZLO) / (float)(TABN - 1))
#define LN2_F    0.69314718055994531f

#define NBLK     512                // co-resident: 8/SM by threads, >=4/SM by regs
#define ENT_PER_BLK (TABN/NBLK)     // 2 zs entries per block
#define WARPS_PER_ENT 4

__device__ float g_L[TABN];
__device__ float g_sC[TABN];   // connected reduced integral (smooth in zs)
__device__ float g_H[TABN];    // disconnected sum, k < KSPLIT only (smooth in zs)
__device__ float g_V[TABN];    // full V at nodes (zs_crit sign crossing only)
__device__ int   g_inv[MINV];  // L-space -> zs-cell starting index
__device__ float g_Lcrit;
__device__ float g_sinv;       // (MINV-1) / L[jmax]
__device__ int   g_jmax;
__device__ unsigned int g_ctr; // arrival counter (reset by epilogue block)
__device__ unsigned int g_gen; // generation (monotone; never reset)

struct Coefs {
    float F1, F2, F3, F4, FLln2;   // f(z) = 1 + F1 z + ... + F4 z^4 + (FLln2*z^4)*lg2(z)
    float c1, c2, c3;              // bp(z) = 1 + c1 z + c2 z^2 + c3 z^3; B = bp^2
};

static __device__ __forceinline__ float frcp(float x){ float r; asm("rcp.approx.f32 %0,%1;"   : "=f"(r) : "f"(x)); return r; }
static __device__ __forceinline__ float frsq(float x){ float r; asm("rsqrt.approx.f32 %0,%1;" : "=f"(r) : "f"(x)); return r; }
static __device__ __forceinline__ float fsqt(float x){ float r; asm("sqrt.approx.f32 %0,%1;"  : "=f"(r) : "f"(x)); return r; }
static __device__ __forceinline__ float flg2(float x){ float r; asm("lg2.approx.f32 %0,%1;"   : "=f"(r) : "f"(x)); return r; }

static __device__ __forceinline__ void make_coefs(float a0, float a1, float b0, float b1, Coefs& C)
{
    float w1 = 2.f*a0;
    float w2 = fmaf(a0, a0, 2.f*a1);
    float w3 = 2.f*a0*a1;
    float w4 = a1*a1;
    C.F1 = (4.f/3.f)*w1;
    C.F2 = 2.f*w2;
    C.F3 = 4.f*w3;
    C.F4 = -(1.f + C.F1 + C.F2 + C.F3);   // f(1)=0 identity
    C.FLln2 = -4.f*w4*LN2_F;
    C.c1 = b0; C.c2 = b1;
    C.c3 = ((a0 + a1) - b0) - b1;
}

static __device__ __forceinline__ float evalf(const Coefs& C, float z, float& z2, float& z4)
{
    z2 = z*z; z4 = z2*z2;
    float p = fmaf(fmaf(fmaf(fmaf(C.F4, z, C.F3), z, C.F2), z, C.F1), z, 1.f);
    return fmaf(C.FLln2*z4, flg2(z), p);
}

// Fused L + Vc integrands at one quadrature point.
static __device__ __forceinline__ void lv_point(const Coefs& C, float zs, float fs, float inv_fs,
                                                float y, float omy2, float inv_w,
                                                float& iL, float& iVc)
{
    float r4 = inv_w*inv_w;
    float z = zs*omy2;
    float z2, z4; float f = evalf(C, z, z2, z4);
    float fr = f*inv_fs;
    float m = fmaxf(r4*fr - 1.f, EPS_F);
    float rm = frsq(m);
    float bp  = fmaf(fmaf(fmaf(C.c3, z, C.c2), z, C.c1), z, 1.f);
    float Dd = (1.f - z2)*(1.f + z2);                 // 1 - z^4
    float rsq = frsq(Dd);
    iL = bp*rsq*rm*y;                                 // sqrt(g)*rm*y
    float rsqf = frsq(fmaxf(f, EPS_F));
    float sfg = fabsf(bp)*rsq*(f*rsqf);               // sqrt(f*bp^2/D)
    float w2 = omy2*omy2; w2 = w2*w2;                 // (1-y^2)^4
    float tt = fmaxf(fmaf(-w2*fs, rsqf*rsqf, 1.f), EPS_F);
    iVc = sfg*inv_w*(frsq(tt) - 1.f)*y;
}

// V disconnected integrand (own grid y2 on [0.001, 1.0])
static __device__ __forceinline__ float vd_point(const Coefs& C, float zs, float y2)
{
    float z = fmaf(zs - 1.f, y2, 1.f);                // 1 - (1-zs)*y2
    float z2, z4; float f = evalf(C, z, z2, z4);
    float bp = fmaf(fmaf(fmaf(C.c3, z, C.c2), z, C.c1), z, 1.f);
    float Dd = (1.f - z2)*(1.f + z2);
    float rsq = frsq(Dd);
    float invD = rsq*rsq;
    float fg = fmaxf(f*(bp*bp)*invD, EPS_F);
    float rz = frcp(z);
    return fsqt(fg)*(rz*rz);
}

// Catmull-Rom interpolation on a gmem table at cell (j, t).
static __device__ __forceinline__ float cr_interp_g(const float* __restrict__ T, int j, float t)
{
    float V0 = __ldg(&T[j]), V1 = __ldg(&T[j+1]);
    float Vm = (j > 0) ? __ldg(&T[j-1]) : V0;
    float Vp = (j+2 < TABN) ? __ldg(&T[j+2]) : V1;
    float dv = V1 - V0;
    float m0 = (j > 0) ? 0.5f*(V1 - Vm) : dv;
    float m1 = (j+2 < TABN) ? 0.5f*(Vp - V0) : dv;
    float e2 = 3.f*dv - 2.f*m0 - m1;
    float e3 = m0 + m1 - 2.f*dv;
    return ((e3*t + e2)*t + m0)*t + V0;
}

// ---------------------------------------------------------------------------
// Single fused kernel:
//  Phase 1: build L / sC / H / V tables (2 zs per block, 4 warps each).
//  Grid barrier (generation counter): last-arriving block runs the slim
//  epilogue (jmax, jcrit -> L_crit, scatter g_inv), then bumps g_gen.
//  Phase 2: one WARP per batch element: inverse-index lookup + Hermite
//  inversion + CR interpolation + exact 64-term disconnected tail (2/lane).
// ---------------------------------------------------------------------------
__global__ void __launch_bounds__(256) k_fused(const float* __restrict__ a,
                                               const float* __restrict__ b,
                                               const float* __restrict__ lc,
                                               const float* __restrict__ Ls,
                                               float* __restrict__ out, int B)
{
    __shared__ float4 tab[NPTS];
    __shared__ float part[8][4];
    __shared__ int s_last, s_jmax, s_jcrit;
    __shared__ unsigned int s_gen;

    // quadrature point table
    {
        const float h = 0.998f/999.f;
        for (int k = threadIdx.x; k < NPTS; k += 256) {
            float y = 0.001f + h*(float)k;
            float omy2 = (1.f - y)*(1.f + y);
            float inv_w = 1.f/(omy2*omy2);
            float W = h;
            if      (k == 0)   W = 0.5f*h + 0.001f + 0.5f*(1.0e-6f)/h;
            else if (k == 1)   W = h - 0.5f*(1.0e-6f)/h;
            else if (k == 999) W = 0.5f*h + 0.5f*(1.f - y);
            tab[k] = make_float4(y, omy2, inv_w, W);
        }
    }
    if (threadIdx.x == 0) s_gen = *(volatile unsigned int*)&g_gen;  // pre-arrival snapshot
    __syncthreads();

    Coefs C; make_coefs(a[0], a[1], b[0], b[1], C);
    float coef = expf(lc[0]);

    int wid  = threadIdx.x >> 5;
    int lane = threadIdx.x & 31;

    // ---------------- Phase 1: table build ----------------
    {
        int e    = wid >> 2;              // entry within block: 0..1
        int quar = wid & 3;               // quarter of the quadrature
        int j = blockIdx.x*ENT_PER_BLK + e;
        float zs = ZLO + DZ*(float)j;

        float zs2, zs4; float fs = evalf(C, zs, zs2, zs4);
        float inv_fs = frcp(fs);

        const float h2 = 0.999f/999.f;
        float sL = 0.f, sC = 0.f, sH = 0.f, sT = 0.f;
        int k0 = quar*250, k1 = k0 + 250;
        for (int k = k0 + lane; k < k1; k += 32) {
            float4 t = tab[k];
            float iL, iVc;
            lv_point(C, zs, fs, inv_fs, t.x, t.y, t.z, iL, iVc);
            sL = fmaf(t.w, iL, sL);
            sC = fmaf(t.w, iVc, sC);
            float y2 = 0.001f + h2*(float)k;
            float W2 = (k == 0) ? (0.0005f + 0.5f*h2) : ((k == 999) ? 0.5f*h2 : h2);
            float vd = W2*vd_point(C, zs, y2);
            if (k < KSPLIT) sH += vd; else sT += vd;
        }
        #pragma unroll
        for (int o = 16; o; o >>= 1) {
            sL += __shfl_xor_sync(0xffffffffu, sL, o);
            sC += __shfl_xor_sync(0xffffffffu, sC, o);
            sH += __shfl_xor_sync(0xffffffffu, sH, o);
            sT += __shfl_xor_sync(0xffffffffu, sT, o);
        }
        if (lane == 0) {
            part[wid][0] = sL; part[wid][1] = sC;
            part[wid][2] = sH; part[wid][3] = sT;
        }
        __syncthreads();
        if (quar == 0 && lane == 0) {
            int w0 = e*WARPS_PER_ENT;
            sL = part[w0][0] + part[w0+1][0] + part[w0+2][0] + part[w0+3][0];
            sC = part[w0][1] + part[w0+1][1] + part[w0+2][1] + part[w0+3][1];
            sH = part[w0][2] + part[w0+1][2] + part[w0+2][2] + part[w0+3][2];
            sT = part[w0][3] + part[w0+1][3] + part[w0+2][3] + part[w0+3][3];
            g_L[j]  = 4.f*zs*sL*INVPI_F;
            g_sC[j] = sC;
            g_H[j]  = sH;
            float Vc = coef*PI_F*4.f*sC/zs;
            float Vd = coef*PI_F*2.f*(1.f - zs)*((sH + sT) + 0.0005f);
            g_V[j]  = Vc - Vd;
        }
        __syncthreads();
    }

    // ---------------- Grid barrier + epilogue ----------------
    if (threadIdx.x == 0) {
        __threadfence();
        unsigned int done = atomicAdd(&g_ctr, 1u);
        s_last = (done == (unsigned int)(NBLK - 1)) ? 1 : 0;
        s_jmax = TABN - 1; s_jcrit = TABN;
    }
    __syncthreads();

    if (s_last) {
        // slim epilogue (this block only)
        __threadfence();
        int tid = threadIdx.x;
        for (int k = tid; k < TABN - 1; k += 256)
            if (__ldg(&g_L[k+1]) < __ldg(&g_L[k])) atomicMin(&s_jmax, k);
        __syncthreads();
        int jmax = s_jmax;
        if (jmax < 1) jmax = 1;

        int j001 = (int)ceilf((0.001f - ZLO)/DZ);
        for (int k = tid; k < jmax; k += 256)
            if (k >= j001 && __ldg(&g_V[k]) <= 0.f && __ldg(&g_V[k+1]) > 0.f) atomicMin(&s_jcrit, k);

        float Lmax = __ldg(&g_L[jmax]);
        float sinv = (float)(MINV - 1) / fmaxf(Lmax, 1e-30f);

        for (int m = tid; m < MINV; m += 256) g_inv[m] = 0;
        __syncthreads();
        for (int k = tid; k < jmax; k += 256) {
            float Lj  = __ldg(&g_L[k]);
            float Lj1 = __ldg(&g_L[k+1]);
            int mm0 = max((int)ceilf(Lj*sinv), 0);
            int mm1 = (k == jmax - 1) ? MINV : min((int)ceilf(Lj1*sinv), MINV);
            for (int m = mm0; m < mm1; ++m) g_inv[m] = k;
        }
        __syncthreads();

        if (tid == 0) {
            int jc = (s_jcrit < TABN) ? s_jcrit : (jmax - 1);
            if (jc < 0) jc = 0;
            float V0 = g_V[jc], V1 = g_V[jc+1];
            float t = (-V0) / fmaxf(V1 - V0, 1e-30f);
            t = fminf(fmaxf(t, 0.f), 1.f);
            float L0 = g_L[jc], L1 = g_L[jc+1];
            float Lm = (jc > 0) ? g_L[jc-1] : L0;
            float Lp = (jc+2 < TABN) ? g_L[jc+2] : L1;
            float d = L1 - L0;
            float m0 = (jc > 0) ? 0.5f*(L1 - Lm) : d;
            float m1 = (jc+2 < TABN) ? 0.5f*(Lp - L0) : d;
            m0 = fmaxf(m0, 0.f); m1 = fmaxf(m1, 0.f);
            float c2 = 3.f*d - 2.f*m0 - m1;
            float c3 = m0 + m1 - 2.f*d;
            g_Lcrit = ((c3*t + c2)*t + m0)*t + L0;
            g_jmax = jmax;
            g_sinv = sinv;
            g_ctr = 0u;                 // reset for next replay
            __threadfence();
            atomicAdd(&g_gen, 1u);      // release
        }
        __syncthreads();
    } else {
        if (threadIdx.x == 0) {
            while (*(volatile unsigned int*)&g_gen == s_gen) __nanosleep(64);
        }
        __syncthreads();
        __threadfence();   // acquire: see epilogue + all blocks' table writes
    }

    // ---------------- Phase 2: solve (one warp per element) ----------------
    float L_crit = *(volatile float*)&g_Lcrit;
    float sinv = g_sinv;
    int jmax = g_jmax;

    int gwarp = blockIdx.x*8 + wid;      // 0..4095
    for (int i = gwarp; i < B; i += NBLK*8) {
        float Lq = __ldg(&Ls[i]);
        bool valid = Lq < L_crit;
        float Leff = valid ? Lq : 0.5f*L_crit;

        // inverse-index lookup + bidirectional fixup
        int idx = min(max((int)(Leff * sinv), 0), MINV - 1);
        int j = __ldg(&g_inv[idx]);
        while (j < jmax - 1 && __ldg(&g_L[j+1]) <= Leff) ++j;
        while (j > 0 && __ldg(&g_L[j]) > Leff) --j;

        // Catmull-Rom Hermite inversion inside cell j
        float L0 = __ldg(&g_L[j]), L1 = __ldg(&g_L[j+1]);
        float Lm = (j > 0) ? __ldg(&g_L[j-1]) : L0;
        float Lp = (j+2 < TABN) ? __ldg(&g_L[j+2]) : L1;
        float d = L1 - L0;
        float m0 = (j > 0) ? 0.5f*(L1 - Lm) : d;
        float m1 = (j+2 < TABN) ? 0.5f*(Lp - L0) : d;
        m0 = fmaxf(m0, 0.f); m1 = fmaxf(m1, 0.f);
        float c2 = 3.f*d - 2.f*m0 - m1;
        float c3 = m0 + m1 - 2.f*d;
        float t = (Leff - L0)*frcp(fmaxf(d, 1e-30f));
        t = fminf(fmaxf(t, 0.f), 1.f);
        #pragma unroll
        for (int it = 0; it < 3; ++it) {
            float H  = ((c3*t + c2)*t + m0)*t + L0 - Leff;
            float Hp = (3.f*c3*t + 2.f*c2)*t + m0;
            t = t - H*frcp(Hp);
            t = fminf(fmaxf(t, 0.f), 1.f);
        }
        float zs = ZLO + DZ*((float)j + t);
        zs = fminf(fmaxf(zs, 1e-4f), 0.9995f);

        // smooth parts
        float sC = cr_interp_g(g_sC, j, t);
        float sH = cr_interp_g(g_H,  j, t);

        // exact tail: lane handles k = KSPLIT + lane, +32 (2 terms)
        const float h2 = 0.999f/999.f;
        float tail = 0.f;
        #pragma unroll
        for (int m = 0; m < KTAIL/32; ++m) {
            int k = KSPLIT + lane + m*32;
            float y2 = 0.001f + h2*(float)k;
            float W2 = (k == NPTS-1) ? 0.5f*h2 : h2;
            tail = fmaf(W2, vd_point(C, zs, y2), tail);
        }
        #pragma unroll
        for (int o = 16; o; o >>= 1) tail += __shfl_xor_sync(0xffffffffu, tail, o);

        float Vc = coef*PI_F*4.f*sC/zs;
        float Vd = coef*PI_F*2.f*(1.f - zs)*((sH + tail) + 0.0005f);
        float V = Vc - Vd;

        if (lane == 0) out[i] = valid ? V : 0.f;
    }
}

extern "C" void kernel_launch(void* const* d_in, const int* in_sizes, int n_in,
                              void* d_out, int out_size)
{
    const float* Ls = (const float*)d_in[0];
    const float* a  = (const float*)d_in[1];
    const float* b  = (const float*)d_in[2];
    const float* lc = (const float*)d_in[3];
    float* out = (float*)d_out;
    int B = in_sizes[0];

    k_fused<<<NBLK, 256>>>(a, b, lc, Ls, out, B);
}

// round 13
// speedup vs baseline: 1.2145x; 1.2145x over previous
#include <cuda_runtime.h>
#include <math.h>

#define PI_F     3.14159265358979f
#define INVPI_F  0.3183098861837907f
#define EPS_F    1e-12f
#define NPTS     1000
#define KTAIL    64                 // last KTAIL reference-grid vd terms: exact
#define KSPLIT   (NPTS - KTAIL)     // 936
#define NPC      500                // coarse quadrature points (table build)
#define NVD      (NPC + KTAIL)      // coarse H points + exact node tail
#define TABN     1024
#define MINV     2048
#define ZLO      1e-4f
#define ZHI      0.9995f
#define DZ       ((ZHI - ZLO) / (float)(TABN - 1))
#define LN2_F    0.69314718055994531f

#define ENT_PER_BLK 2
#define WARPS_PER_ENT 4
#define TBLOCKS  (TABN / ENT_PER_BLK)

__device__ float g_L[TABN];
__device__ float g_sC[TABN];   // connected reduced integral (smooth in zs)
__device__ float g_H[TABN];    // disconnected sum over [0.001, 0.936] (smooth in zs)
__device__ float g_V[TABN];    // full V at nodes (zs_crit crossing only)
__device__ int   g_inv[MINV];  // L-space -> zs-cell starting index
__device__ float g_Lcrit;
__device__ float g_sinv;
__device__ int   g_jmax;
__device__ unsigned int g_ctr;

struct Coefs {
    float F1, F2, F3, F4, FLln2;   // f(z) = 1 + F1 z + ... + F4 z^4 + (FLln2*z^4)*lg2(z)
    float c1, c2, c3;              // bp(z) = 1 + c1 z + c2 z^2 + c3 z^3
};

static __device__ __forceinline__ float frcp(float x){ float r; asm("rcp.approx.f32 %0,%1;"   : "=f"(r) : "f"(x)); return r; }
static __device__ __forceinline__ float frsq(float x){ float r; asm("rsqrt.approx.f32 %0,%1;" : "=f"(r) : "f"(x)); return r; }
static __device__ __forceinline__ float fsqt(float x){ float r; asm("sqrt.approx.f32 %0,%1;"  : "=f"(r) : "f"(x)); return r; }
static __device__ __forceinline__ float flg2(float x){ float r; asm("lg2.approx.f32 %0,%1;"   : "=f"(r) : "f"(x)); return r; }

static __device__ __forceinline__ void make_coefs(float a0, float a1, float b0, float b1, Coefs& C)
{
    float w1 = 2.f*a0;
    float w2 = fmaf(a0, a0, 2.f*a1);
    float w3 = 2.f*a0*a1;
    float w4 = a1*a1;
    C.F1 = (4.f/3.f)*w1;
    C.F2 = 2.f*w2;
    C.F3 = 4.f*w3;
    C.F4 = -(1.f + C.F1 + C.F2 + C.F3);   // f(1)=0 identity
    C.FLln2 = -4.f*w4*LN2_F;
    C.c1 = b0; C.c2 = b1;
    C.c3 = ((a0 + a1) - b0) - b1;
}

static __device__ __forceinline__ float evalf(const Coefs& C, float z, float& z2, float& z4)
{
    z2 = z*z; z4 = z2*z2;
    float p = fmaf(fmaf(fmaf(fmaf(C.F4, z, C.F3), z, C.F2), z, C.F1), z, 1.f);
    return fmaf(C.FLln2*z4, flg2(z), p);
}

// Fused L + Vc integrands at one quadrature point.
static __device__ __forceinline__ void lv_point(const Coefs& C, float zs, float fs, float inv_fs,
                                                float y, float omy2, float inv_w,
                                                float& iL, float& iVc)
{
    float r4 = inv_w*inv_w;
    float z = zs*omy2;
    float z2, z4; float f = evalf(C, z, z2, z4);
    float fr = f*inv_fs;
    float m = fmaxf(r4*fr - 1.f, EPS_F);
    float rm = frsq(m);
    float bp  = fmaf(fmaf(fmaf(C.c3, z, C.c2), z, C.c1), z, 1.f);
    float Dd = (1.f - z2)*(1.f + z2);
    float rsq = frsq(Dd);
    iL = bp*rsq*rm*y;
    float rsqf = frsq(fmaxf(f, EPS_F));
    float sfg = fabsf(bp)*rsq*(f*rsqf);
    float w2 = omy2*omy2; w2 = w2*w2;
    float tt = fmaxf(fmaf(-w2*fs, rsqf*rsqf, 1.f), EPS_F);
    iVc = sfg*inv_w*(frsq(tt) - 1.f)*y;
}

// V disconnected integrand on a y2 grid point.
static __device__ __forceinline__ float vd_point(const Coefs& C, float zs, float y2)
{
    float z = fmaf(zs - 1.f, y2, 1.f);
    float z2, z4; float f = evalf(C, z, z2, z4);
    float bp = fmaf(fmaf(fmaf(C.c3, z, C.c2), z, C.c1), z, 1.f);
    float Dd = (1.f - z2)*(1.f + z2);
    float rsq = frsq(Dd);
    float invD = rsq*rsq;
    float fg = fmaxf(f*(bp*bp)*invD, EPS_F);
    float rz = frcp(z);
    return fsqt(fg)*(rz*rz);
}

// Catmull-Rom interpolation on a gmem table at cell (j, t).
static __device__ __forceinline__ float cr_interp_g(const float* __restrict__ T, int j, float t)
{
    float V0 = __ldg(&T[j]), V1 = __ldg(&T[j+1]);
    float Vm = (j > 0) ? __ldg(&T[j-1]) : V0;
    float Vp = (j+2 < TABN) ? __ldg(&T[j+2]) : V1;
    float dv = V1 - V0;
    float m0 = (j > 0) ? 0.5f*(V1 - Vm) : dv;
    float m1 = (j+2 < TABN) ? 0.5f*(Vp - V0) : dv;
    float e2 = 3.f*dv - 2.f*m0 - m1;
    float e3 = m0 + m1 - 2.f*dv;
    return ((e3*t + e2)*t + m0)*t + V0;
}

// ---------------------------------------------------------------------------
// k_table: coarse 500-pt quadrature for L/sC/H + exact 64-term node tail.
// 4 warps per zs entry, 2 entries per 256-thread block.
// Last-finishing block runs the slim epilogue.
// ---------------------------------------------------------------------------
__global__ void __launch_bounds__(256) k_table(const float* __restrict__ a,
                                               const float* __restrict__ b,
                                               const float* __restrict__ lc)
{
    __shared__ float4 tabL[NPC];    // y, (1-y)(1+y), (1-y^2)^-2, weight (coarse + _extend folded)
    __shared__ float2 tabD[NVD];    // y2, weight (coarse H grid + exact ref tail)
    __shared__ float part[8][4];
    __shared__ int s_last, s_jmax, s_jcrit;

    {
        const float hc  = 0.998f/499.f;          // coarse y grid [0.001, 0.999]
        const float h2c = 0.935f/499.f;          // coarse y2 grid [0.001, 0.936]
        for (int k = threadIdx.x; k < NVD; k += 256) {
            if (k < NPC) {
                float y = 0.001f + hc*(float)k;
                float omy2 = (1.f - y)*(1.f + y);
                float inv_w = 1.f/(omy2*omy2);
                float W = hc;
                if      (k == 0)       W = 0.5f*hc + 0.001f + 0.5f*(1.0e-6f)/hc;
                else if (k == 1)       W = hc - 0.5f*(1.0e-6f)/hc;
                else if (k == NPC-1)   W = 0.5f*hc + 0.0005f;
                tabL[k] = make_float4(y, omy2, inv_w, W);

                float y2 = 0.001f + h2c*(float)k;
                float W2 = h2c;
                if      (k == 0)       W2 = 0.0005f + 0.5f*h2c;        // 0.5e-3*G(0.001) + coarse half
                else if (k == NPC-1)   W2 = 0.5f*h2c + 0.0005f;        // coarse half + ref half-seg [935,936]
                tabD[k] = make_float2(y2, W2);
            } else {
                int kr = k + (KSPLIT - NPC);     // 936..999 on the reference grid
                float y2 = 0.001f + 0.001f*(float)kr;
                float W2 = (kr == NPTS-1) ? 0.0005f : 0.001f;
                tabD[k] = make_float2(y2, W2);
            }
        }
    }
    __syncthreads();

    Coefs C; make_coefs(a[0], a[1], b[0], b[1], C);
    float coef = expf(lc[0]);

    int wid  = threadIdx.x >> 5;
    int lane = threadIdx.x & 31;
    int e    = wid >> 2;
    int quar = wid & 3;
    int j = blockIdx.x*ENT_PER_BLK + e;
    float zs = ZLO + DZ*(float)j;

    float zs2, zs4; float fs = evalf(C, zs, zs2, zs4);
    float inv_fs = frcp(fs);

    float sL = 0.f, sC = 0.f, sH = 0.f, sT = 0.f;
    int off = quar*32 + lane;
    for (int k = off; k < NPC; k += 128) {
        float4 t = tabL[k];
        float iL, iVc;
        lv_point(C, zs, fs, inv_fs, t.x, t.y, t.z, iL, iVc);
        sL = fmaf(t.w, iL, sL);
        sC = fmaf(t.w, iVc, sC);
    }
    for (int k = off; k < NVD; k += 128) {
        float2 t = tabD[k];
        float vd = t.y * vd_point(C, zs, t.x);
        if (k < NPC) sH += vd; else sT += vd;
    }
    #pragma unroll
    for (int o = 16; o; o >>= 1) {
        sL += __shfl_xor_sync(0xffffffffu, sL, o);
        sC += __shfl_xor_sync(0xffffffffu, sC, o);
        sH += __shfl_xor_sync(0xffffffffu, sH, o);
        sT += __shfl_xor_sync(0xffffffffu, sT, o);
    }
    if (lane == 0) {
        part[wid][0] = sL; part[wid][1] = sC;
        part[wid][2] = sH; part[wid][3] = sT;
    }
    __syncthreads();
    if (quar == 0 && lane == 0) {
        int w0 = e*WARPS_PER_ENT;
        sL = part[w0][0] + part[w0+1][0] + part[w0+2][0] + part[w0+3][0];
        sC = part[w0][1] + part[w0+1][1] + part[w0+2][1] + part[w0+3][1];
        sH = part[w0][2] + part[w0+1][2] + part[w0+2][2] + part[w0+3][2];
        sT = part[w0][3] + part[w0+1][3] + part[w0+2][3] + part[w0+3][3];
        g_L[j]  = 4.f*zs*sL*INVPI_F;
        g_sC[j] = sC;
        g_H[j]  = sH;
        float Vc = coef*PI_F*4.f*sC/zs;
        float Vd = coef*PI_F*2.f*(1.f - zs)*((sH + sT) + 0.0005f);
        g_V[j]  = Vc - Vd;
    }
    __syncthreads();

    // last-block-done: slim scalar epilogue
    if (threadIdx.x == 0) {
        __threadfence();
        unsigned int done = atomicAdd(&g_ctr, 1u);
        s_last = (done == (unsigned int)(gridDim.x - 1)) ? 1 : 0;
        s_jmax = TABN - 1; s_jcrit = TABN;
    }
    __syncthreads();
    if (!s_last) return;
    __threadfence();

    int tid = threadIdx.x;
    for (int k = tid; k < TABN - 1; k += 256)
        if (__ldg(&g_L[k+1]) < __ldg(&g_L[k])) atomicMin(&s_jmax, k);
    __syncthreads();
    int jmax = s_jmax;
    if (jmax < 1) jmax = 1;

    int j001 = (int)ceilf((0.001f - ZLO)/DZ);
    for (int k = tid; k < jmax; k += 256)
        if (k >= j001 && __ldg(&g_V[k]) <= 0.f && __ldg(&g_V[k+1]) > 0.f) atomicMin(&s_jcrit, k);

    float Lmax = __ldg(&g_L[jmax]);
    float sinv = (float)(MINV - 1) / fmaxf(Lmax, 1e-30f);

    for (int m = tid; m < MINV; m += 256) g_inv[m] = 0;
    __syncthreads();
    for (int k = tid; k < jmax; k += 256) {
        float Lj  = __ldg(&g_L[k]);
        float Lj1 = __ldg(&g_L[k+1]);
        int mm0 = max((int)ceilf(Lj*sinv), 0);
        int mm1 = (k == jmax - 1) ? MINV : min((int)ceilf(Lj1*sinv), MINV);
        for (int m = mm0; m < mm1; ++m) g_inv[m] = k;
    }
    __syncthreads();

    if (tid == 0) {
        int jc = (s_jcrit < TABN) ? s_jcrit : (jmax - 1);
        if (jc < 0) jc = 0;
        float V0 = g_V[jc], V1 = g_V[jc+1];
        float t = (-V0) / fmaxf(V1 - V0, 1e-30f);
        t = fminf(fmaxf(t, 0.f), 1.f);
        float L0 = g_L[jc], L1 = g_L[jc+1];
        float Lm = (jc > 0) ? g_L[jc-1] : L0;
        float Lp = (jc+2 < TABN) ? g_L[jc+2] : L1;
        float d = L1 - L0;
        float m0 = (jc > 0) ? 0.5f*(L1 - Lm) : d;
        float m1 = (jc+2 < TABN) ? 0.5f*(Lp - L0) : d;
        m0 = fmaxf(m0, 0.f); m1 = fmaxf(m1, 0.f);
        float c2 = 3.f*d - 2.f*m0 - m1;
        float c3 = m0 + m1 - 2.f*d;
        g_Lcrit = ((c3*t + c2)*t + m0)*t + L0;
        g_jmax = jmax;
        g_sinv = sinv;
        g_ctr = 0u;
    }
}

// ---------------------------------------------------------------------------
// k_solve (R10 shape): 8 lanes per element, inverse-index lookup, exact
// reference-grid 64-term tail split 8 ways.
// ---------------------------------------------------------------------------
__global__ void __launch_bounds__(256) k_solve(const float* __restrict__ Ls,
                                               const float* __restrict__ a,
                                               const float* __restrict__ b,
                                               const float* __restrict__ lc,
                                               float* __restrict__ out, int B)
{
    int lane = threadIdx.x & 31;
    int sub  = lane >> 3;
    int r    = lane & 7;
    int warp_g = (blockIdx.x*256 + threadIdx.x) >> 5;
    int i = warp_g*4 + sub;
    if (i >= B) return;

    Coefs C; make_coefs(a[0], a[1], b[0], b[1], C);
    float coef = expf(lc[0]);
    float L_crit = g_Lcrit;
    float sinv = g_sinv;
    int jmax = g_jmax;

    float Lq = __ldg(&Ls[i]);
    bool valid = Lq < L_crit;
    float Leff = valid ? Lq : 0.5f*L_crit;

    // inverse-index lookup + bidirectional fixup
    int idx = min(max((int)(Leff * sinv), 0), MINV - 1);
    int j = __ldg(&g_inv[idx]);
    while (j < jmax - 1 && __ldg(&g_L[j+1]) <= Leff) ++j;
    while (j > 0 && __ldg(&g_L[j]) > Leff) --j;

    // Catmull-Rom Hermite inversion inside cell j
    float L0 = __ldg(&g_L[j]), L1 = __ldg(&g_L[j+1]);
    float Lm = (j > 0) ? __ldg(&g_L[j-1]) : L0;
    float Lp = (j+2 < TABN) ? __ldg(&g_L[j+2]) : L1;
    float d = L1 - L0;
    float m0 = (j > 0) ? 0.5f*(L1 - Lm) : d;
    float m1 = (j+2 < TABN) ? 0.5f*(Lp - L0) : d;
    m0 = fmaxf(m0, 0.f); m1 = fmaxf(m1, 0.f);
    float c2 = 3.f*d - 2.f*m0 - m1;
    float c3 = m0 + m1 - 2.f*d;
    float t = (Leff - L0)*frcp(fmaxf(d, 1e-30f));
    t = fminf(fmaxf(t, 0.f), 1.f);
    #pragma unroll
    for (int it = 0; it < 3; ++it) {
        float H  = ((c3*t + c2)*t + m0)*t + L0 - Leff;
        float Hp = (3.f*c3*t + 2.f*c2)*t + m0;
        t = t - H*frcp(Hp);
        t = fminf(fmaxf(t, 0.f), 1.f);
    }
    float zs = ZLO + DZ*((float)j + t);
    zs = fminf(fmaxf(zs, 1e-4f), 0.9995f);

    // smooth parts interpolated
    float sC = cr_interp_g(g_sC, j, t);
    float sH = cr_interp_g(g_H,  j, t);

    // exact reference-grid tail: lane r handles k = KSPLIT + r, r+8, ...
    const float h2 = 0.999f/999.f;
    float tail = 0.f;
    #pragma unroll
    for (int m = 0; m < KTAIL/8; ++m) {
        int k = KSPLIT + r + m*8;
        float y2 = 0.001f + h2*(float)k;
        float W2 = (k == NPTS-1) ? 0.5f*h2 : h2;
        tail = fmaf(W2, vd_point(C, zs, y2), tail);
    }
    #pragma unroll
    for (int o = 4; o; o >>= 1) tail += __shfl_xor_sync(0xffffffffu, tail, o);

    float Vc = coef*PI_F*4.f*sC/zs;
    float Vd = coef*PI_F*2.f*(1.f - zs)*((sH + tail) + 0.0005f);
    float V = Vc - Vd;

    if (r == 0) out[i] = valid ? V : 0.f;
}

extern "C" void kernel_launch(void* const* d_in, const int* in_sizes, int n_in,
                              void* d_out, int out_size)
{
    const float* Ls = (const float*)d_in[0];
    const float* a  = (const float*)d_in[1];
    const float* b  = (const float*)d_in[2];
    const float* lc = (const float*)d_in[3];
    float* out = (float*)d_out;
    int B = in_sizes[0];

    k_table<<<TBLOCKS, 256>>>(a, b, lc);
    int blocks = (B + 31)/32;     // 8 warps * 4 elements per block
    if (blocks > 0)
        k_solve<<<blocks, 256>>>(Ls, a, b, lc, out, B);
}

// round 14
// speedup vs baseline: 1.3439x; 1.1065x over previous
#include <cuda_runtime.h>
#include <math.h>

#define PI_F     3.14159265358979f
#define INVPI_F  0.3183098861837907f
#define EPS_F    1e-12f
#define NPTS     1000
#define KTAIL    64                 // last KTAIL reference-grid vd terms: exact
#define KSPLIT   (NPTS - KTAIL)     // 936
#define NPC      250                // coarse quadrature points (table build)
#define NVD      (NPC + KTAIL)      // coarse H points + exact node tail
#define TABN     1024
#define MINV     2048
#define ZLO      1e-4f
#define ZHI      0.9995f
#define DZ       ((ZHI - ZLO) / (float)(TABN - 1))
#define LN2_F    0.69314718055994531f

#define ENT_PER_BLK 2
#define WARPS_PER_ENT 4
#define TBLOCKS  (TABN / ENT_PER_BLK)

__device__ float g_L[TABN];
__device__ float g_sC[TABN];   // connected reduced integral (smooth in zs)
__device__ float g_H[TABN];    // disconnected sum over [0.001, 0.936] (smooth in zs)
__device__ float g_V[TABN];    // full V at nodes (zs_crit crossing only)
__device__ int   g_inv[MINV];  // L-space -> zs-cell starting index
__device__ float g_Lcrit;
__device__ float g_sinv;
__device__ int   g_jmax;
__device__ unsigned int g_ctr;

struct Coefs {
    float F1, F2, F3, F4, FLln2;   // f(z) = 1 + F1 z + ... + F4 z^4 + (FLln2*z^4)*lg2(z)
    float c1, c2, c3;              // bp(z) = 1 + c1 z + c2 z^2 + c3 z^3
};

static __device__ __forceinline__ float frcp(float x){ float r; asm("rcp.approx.f32 %0,%1;"   : "=f"(r) : "f"(x)); return r; }
static __device__ __forceinline__ float frsq(float x){ float r; asm("rsqrt.approx.f32 %0,%1;" : "=f"(r) : "f"(x)); return r; }
static __device__ __forceinline__ float fsqt(float x){ float r; asm("sqrt.approx.f32 %0,%1;"  : "=f"(r) : "f"(x)); return r; }
static __device__ __forceinline__ float flg2(float x){ float r; asm("lg2.approx.f32 %0,%1;"   : "=f"(r) : "f"(x)); return r; }

static __device__ __forceinline__ void make_coefs(float a0, float a1, float b0, float b1, Coefs& C)
{
    float w1 = 2.f*a0;
    float w2 = fmaf(a0, a0, 2.f*a1);
    float w3 = 2.f*a0*a1;
    float w4 = a1*a1;
    C.F1 = (4.f/3.f)*w1;
    C.F2 = 2.f*w2;
    C.F3 = 4.f*w3;
    C.F4 = -(1.f + C.F1 + C.F2 + C.F3);   // f(1)=0 identity
    C.FLln2 = -4.f*w4*LN2_F;
    C.c1 = b0; C.c2 = b1;
    C.c3 = ((a0 + a1) - b0) - b1;
}

static __device__ __forceinline__ float evalf(const Coefs& C, float z, float& z2, float& z4)
{
    z2 = z*z; z4 = z2*z2;
    float p = fmaf(fmaf(fmaf(fmaf(C.F4, z, C.F3), z, C.F2), z, C.F1), z, 1.f);
    return fmaf(C.FLln2*z4, flg2(z), p);
}

// Fused L + Vc integrands at one quadrature point.
static __device__ __forceinline__ void lv_point(const Coefs& C, float zs, float fs, float inv_fs,
                                                float y, float omy2, float inv_w,
                                                float& iL, float& iVc)
{
    float r4 = inv_w*inv_w;
    float z = zs*omy2;
    float z2, z4; float f = evalf(C, z, z2, z4);
    float fr = f*inv_fs;
    float m = fmaxf(r4*fr - 1.f, EPS_F);
    float rm = frsq(m);
    float bp  = fmaf(fmaf(fmaf(C.c3, z, C.c2), z, C.c1), z, 1.f);
    float Dd = (1.f - z2)*(1.f + z2);
    float rsq = frsq(Dd);
    iL = bp*rsq*rm*y;
    float rsqf = frsq(fmaxf(f, EPS_F));
    float sfg = fabsf(bp)*rsq*(f*rsqf);
    float w2 = omy2*omy2; w2 = w2*w2;
    float tt = fmaxf(fmaf(-w2*fs, rsqf*rsqf, 1.f), EPS_F);
    iVc = sfg*inv_w*(frsq(tt) - 1.f)*y;
}

// V disconnected integrand on a y2 grid point.
static __device__ __forceinline__ float vd_point(const Coefs& C, float zs, float y2)
{
    float z = fmaf(zs - 1.f, y2, 1.f);
    float z2, z4; float f = evalf(C, z, z2, z4);
    float bp = fmaf(fmaf(fmaf(C.c3, z, C.c2), z, C.c1), z, 1.f);
    float Dd = (1.f - z2)*(1.f + z2);
    float rsq = frsq(Dd);
    float invD = rsq*rsq;
    float fg = fmaxf(f*(bp*bp)*invD, EPS_F);
    float rz = frcp(z);
    return fsqt(fg)*(rz*rz);
}

// Catmull-Rom interpolation on a gmem table at cell (j, t).
static __device__ __forceinline__ float cr_interp_g(const float* __restrict__ T, int j, float t)
{
    float V0 = __ldg(&T[j]), V1 = __ldg(&T[j+1]);
    float Vm = (j > 0) ? __ldg(&T[j-1]) : V0;
    float Vp = (j+2 < TABN) ? __ldg(&T[j+2]) : V1;
    float dv = V1 - V0;
    float m0 = (j > 0) ? 0.5f*(V1 - Vm) : dv;
    float m1 = (j+2 < TABN) ? 0.5f*(Vp - V0) : dv;
    float e2 = 3.f*dv - 2.f*m0 - m1;
    float e3 = m0 + m1 - 2.f*dv;
    return ((e3*t + e2)*t + m0)*t + V0;
}

// ---------------------------------------------------------------------------
// k_table: coarse 250-pt quadrature for L/sC/H + exact 64-term node tail.
// 4 warps per zs entry, 2 entries per 256-thread block.
// Last-finishing block runs the slim epilogue.
// ---------------------------------------------------------------------------
__global__ void __launch_bounds__(256) k_table(const float* __restrict__ a,
                                               const float* __restrict__ b,
                                               const float* __restrict__ lc)
{
    __shared__ float4 tabL[NPC];    // y, (1-y)(1+y), (1-y^2)^-2, weight (_extend folded)
    __shared__ float2 tabD[NVD];    // y2, weight (coarse H grid + exact ref tail)
    __shared__ float part[8][4];
    __shared__ int s_last, s_jmax, s_jcrit;

    {
        const float hc  = 0.998f/(float)(NPC - 1);   // coarse y grid [0.001, 0.999]
        const float h2c = 0.935f/(float)(NPC - 1);   // coarse y2 grid [0.001, 0.936]
        for (int k = threadIdx.x; k < NVD; k += 256) {
            if (k < NPC) {
                float y = 0.001f + hc*(float)k;
                float omy2 = (1.f - y)*(1.f + y);
                float inv_w = 1.f/(omy2*omy2);
                float W = hc;
                if      (k == 0)       W = 0.5f*hc + 0.001f + 0.5f*(1.0e-6f)/hc;
                else if (k == 1)       W = hc - 0.5f*(1.0e-6f)/hc;
                else if (k == NPC-1)   W = 0.5f*hc + 0.0005f;
                tabL[k] = make_float4(y, omy2, inv_w, W);

                float y2 = 0.001f + h2c*(float)k;
                float W2 = h2c;
                if      (k == 0)       W2 = 0.0005f + 0.5f*h2c;
                else if (k == NPC-1)   W2 = 0.5f*h2c + 0.0005f;
                tabD[k] = make_float2(y2, W2);
            } else {
                int kr = k + (KSPLIT - NPC);     // 936..999 on the reference grid
                float y2 = 0.001f + 0.001f*(float)kr;
                float W2 = (kr == NPTS-1) ? 0.0005f : 0.001f;
                tabD[k] = make_float2(y2, W2);
            }
        }
    }
    __syncthreads();

    Coefs C; make_coefs(a[0], a[1], b[0], b[1], C);
    float coef = expf(lc[0]);

    int wid  = threadIdx.x >> 5;
    int lane = threadIdx.x & 31;
    int e    = wid >> 2;
    int quar = wid & 3;
    int j = blockIdx.x*ENT_PER_BLK + e;
    float zs = ZLO + DZ*(float)j;

    float zs2, zs4; float fs = evalf(C, zs, zs2, zs4);
    float inv_fs = frcp(fs);

    float sL = 0.f, sC = 0.f, sH = 0.f, sT = 0.f;
    int off = quar*32 + lane;
    for (int k = off; k < NPC; k += 128) {
        float4 t = tabL[k];
        float iL, iVc;
        lv_point(C, zs, fs, inv_fs, t.x, t.y, t.z, iL, iVc);
        sL = fmaf(t.w, iL, sL);
        sC = fmaf(t.w, iVc, sC);
    }
    for (int k = off; k < NVD; k += 128) {
        float2 t = tabD[k];
        float vd = t.y * vd_point(C, zs, t.x);
        if (k < NPC) sH += vd; else sT += vd;
    }
    #pragma unroll
    for (int o = 16; o; o >>= 1) {
        sL += __shfl_xor_sync(0xffffffffu, sL, o);
        sC += __shfl_xor_sync(0xffffffffu, sC, o);
        sH += __shfl_xor_sync(0xffffffffu, sH, o);
        sT += __shfl_xor_sync(0xffffffffu, sT, o);
    }
    if (lane == 0) {
        part[wid][0] = sL; part[wid][1] = sC;
        part[wid][2] = sH; part[wid][3] = sT;
    }
    __syncthreads();
    if (quar == 0 && lane == 0) {
        int w0 = e*WARPS_PER_ENT;
        sL = part[w0][0] + part[w0+1][0] + part[w0+2][0] + part[w0+3][0];
        sC = part[w0][1] + part[w0+1][1] + part[w0+2][1] + part[w0+3][1];
        sH = part[w0][2] + part[w0+1][2] + part[w0+2][2] + part[w0+3][2];
        sT = part[w0][3] + part[w0+1][3] + part[w0+2][3] + part[w0+3][3];
        g_L[j]  = 4.f*zs*sL*INVPI_F;
        g_sC[j] = sC;
        g_H[j]  = sH;
        float Vc = coef*PI_F*4.f*sC/zs;
        float Vd = coef*PI_F*2.f*(1.f - zs)*((sH + sT) + 0.0005f);
        g_V[j]  = Vc - Vd;
    }
    __syncthreads();

    // last-block-done: slim scalar epilogue
    if (threadIdx.x == 0) {
        __threadfence();
        unsigned int done = atomicAdd(&g_ctr, 1u);
        s_last = (done == (unsigned int)(gridDim.x - 1)) ? 1 : 0;
        s_jmax = TABN - 1; s_jcrit = TABN;
    }
    __syncthreads();
    if (!s_last) return;
    __threadfence();

    int tid = threadIdx.x;
    for (int k = tid; k < TABN - 1; k += 256)
        if (__ldg(&g_L[k+1]) < __ldg(&g_L[k])) atomicMin(&s_jmax, k);
    __syncthreads();
    int jmax = s_jmax;
    if (jmax < 1) jmax = 1;

    int j001 = (int)ceilf((0.001f - ZLO)/DZ);
    for (int k = tid; k < jmax; k += 256)
        if (k >= j001 && __ldg(&g_V[k]) <= 0.f && __ldg(&g_V[k+1]) > 0.f) atomicMin(&s_jcrit, k);

    float Lmax = __ldg(&g_L[jmax]);
    float sinv = (float)(MINV - 1) / fmaxf(Lmax, 1e-30f);

    for (int m = tid; m < MINV; m += 256) g_inv[m] = 0;
    __syncthreads();
    for (int k = tid; k < jmax; k += 256) {
        float Lj  = __ldg(&g_L[k]);
        float Lj1 = __ldg(&g_L[k+1]);
        int mm0 = max((int)ceilf(Lj*sinv), 0);
        int mm1 = (k == jmax - 1) ? MINV : min((int)ceilf(Lj1*sinv), MINV);
        for (int m = mm0; m < mm1; ++m) g_inv[m] = k;
    }
    __syncthreads();

    if (tid == 0) {
        int jc = (s_jcrit < TABN) ? s_jcrit : (jmax - 1);
        if (jc < 0) jc = 0;
        float V0 = g_V[jc], V1 = g_V[jc+1];
        float t = (-V0) / fmaxf(V1 - V0, 1e-30f);
        t = fminf(fmaxf(t, 0.f), 1.f);
        float L0 = g_L[jc], L1 = g_L[jc+1];
        float Lm = (jc > 0) ? g_L[jc-1] : L0;
        float Lp = (jc+2 < TABN) ? g_L[jc+2] : L1;
        float d = L1 - L0;
        float m0 = (jc > 0) ? 0.5f*(L1 - Lm) : d;
        float m1 = (jc+2 < TABN) ? 0.5f*(Lp - L0) : d;
        m0 = fmaxf(m0, 0.f); m1 = fmaxf(m1, 0.f);
        float c2 = 3.f*d - 2.f*m0 - m1;
        float c3 = m0 + m1 - 2.f*d;
        g_Lcrit = ((c3*t + c2)*t + m0)*t + L0;
        g_jmax = jmax;
        g_sinv = sinv;
        g_ctr = 0u;
    }
}

// ---------------------------------------------------------------------------
// k_solve: 8 lanes per element, inverse-index lookup with BATCHED fixup,
// exact reference-grid 64-term tail split 8 ways.
// ---------------------------------------------------------------------------
__global__ void __launch_bounds__(256) k_solve(const float* __restrict__ Ls,
                                               const float* __restrict__ a,
                                               const float* __restrict__ b,
                                               const float* __restrict__ lc,
                                               float* __restrict__ out, int B)
{
    int lane = threadIdx.x & 31;
    int sub  = lane >> 3;
    int r    = lane & 7;
    int warp_g = (blockIdx.x*256 + threadIdx.x) >> 5;
    int i = warp_g*4 + sub;
    if (i >= B) return;

    Coefs C; make_coefs(a[0], a[1], b[0], b[1], C);
    float coef = expf(lc[0]);
    float L_crit = g_Lcrit;
    float sinv = g_sinv;
    int jmax = g_jmax;

    float Lq = __ldg(&Ls[i]);
    bool valid = Lq < L_crit;
    float Leff = valid ? Lq : 0.5f*L_crit;

    // inverse-index lookup + batched fixup (4 parallel speculative loads)
    int idx = min(max((int)(Leff * sinv), 0), MINV - 1);
    int j = __ldg(&g_inv[idx]);
    {
        float a1 = (j+1 <= jmax) ? __ldg(&g_L[j+1]) : 3.4e38f;
        float a2 = (j+2 <= jmax) ? __ldg(&g_L[j+2]) : 3.4e38f;
        float a3 = (j+3 <= jmax) ? __ldg(&g_L[j+3]) : 3.4e38f;
        float a4 = (j+4 <= jmax) ? __ldg(&g_L[j+4]) : 3.4e38f;
        int step = (a1 <= Leff) + (a2 <= Leff) + (a3 <= Leff) + (a4 <= Leff);
        j = min(j + step, jmax - 1);
    }
    while (j < jmax - 1 && __ldg(&g_L[j+1]) <= Leff) ++j;  // rare fallback
    while (j > 0 && __ldg(&g_L[j]) > Leff) --j;            // rounding guard

    // Catmull-Rom Hermite inversion inside cell j
    float L0 = __ldg(&g_L[j]), L1 = __ldg(&g_L[j+1]);
    float Lm = (j > 0) ? __ldg(&g_L[j-1]) : L0;
    float Lp = (j+2 < TABN) ? __ldg(&g_L[j+2]) : L1;
    float d = L1 - L0;
    float m0 = (j > 0) ? 0.5f*(L1 - Lm) : d;
    float m1 = (j+2 < TABN) ? 0.5f*(Lp - L0) : d;
    m0 = fmaxf(m0, 0.f); m1 = fmaxf(m1, 0.f);
    float c2 = 3.f*d - 2.f*m0 - m1;
    float c3 = m0 + m1 - 2.f*d;
    float t = (Leff - L0)*frcp(fmaxf(d, 1e-30f));
    t = fminf(fmaxf(t, 0.f), 1.f);
    #pragma unroll
    for (int it = 0; it < 3; ++it) {
        float H  = ((c3*t + c2)*t + m0)*t + L0 - Leff;
        float Hp = (3.f*c3*t + 2.f*c2)*t + m0;
        t = t - H*frcp(Hp);
        t = fminf(fmaxf(t, 0.f), 1.f);
    }
    float zs = ZLO + DZ*((float)j + t);
    zs = fminf(fmaxf(zs, 1e-4f), 0.9995f);

    // smooth parts interpolated
    float sC = cr_interp_g(g_sC, j, t);
    float sH = cr_interp_g(g_H,  j, t);

    // exact reference-grid tail: lane r handles k = KSPLIT + r, r+8, ...
    const float h2 = 0.999f/999.f;
    float tail = 0.f;
    #pragma unroll
    for (int m = 0; m < KTAIL/8; ++m) {
        int k = KSPLIT + r + m*8;
        float y2 = 0.001f + h2*(float)k;
        float W2 = (k == NPTS-1) ? 0.5f*h2 : h2;
        tail = fmaf(W2, vd_point(C, zs, y2), tail);
    }
    #pragma unroll
    for (int o = 4; o; o >>= 1) tail += __shfl_xor_sync(0xffffffffu, tail, o);

    float Vc = coef*PI_F*4.f*sC/zs;
    float Vd = coef*PI_F*2.f*(1.f - zs)*((sH + tail) + 0.0005f);
    float V = Vc - Vd;

    if (r == 0) out[i] = valid ? V : 0.f;
}

extern "C" void kernel_launch(void* const* d_in, const int* in_sizes, int n_in,
                              void* d_out, int out_size)
{
    const float* Ls = (const float*)d_in[0];
    const float* a  = (const float*)d_in[1];
    const float* b  = (const float*)d_in[2];
    const float* lc = (const float*)d_in[3];
    float* out = (float*)d_out;
    int B = in_sizes[0];

    k_table<<<TBLOCKS, 256>>>(a, b, lc);
    int blocks = (B + 31)/32;     // 8 warps * 4 elements per block
    if (blocks > 0)
        k_solve<<<blocks, 256>>>(Ls, a, b, lc, out, B);
}